// round 1
// baseline (speedup 1.0000x reference)
#include <cuda_runtime.h>

#define BB 16
#define NN 1024
#define INP 256
#define HEADS 8
#define DMH 32
#define INNER 256
#define OUP 256
#define NSQ (NN * NN)

// ---------------- device scratch (allocation-free) ----------------
__device__ float g_q[BB * HEADS * NN * DMH];      // 16 MB, scale pre-applied
__device__ float g_k[BB * HEADS * NN * DMH];      // 16 MB
__device__ float g_v[BB * HEADS * NN * DMH];      // 16 MB
__device__ float g_attn[BB * NN * INNER];         // 16 MB (b, n, h*32+d)
__device__ float g_bias[HEADS * NSQ];             // 32 MB (h, i, j)

// ---------------- kernel 0: bias gather precompute ----------------
__global__ __launch_bounds__(256) void bias_kernel(const int* __restrict__ rel,
                                                   const float* __restrict__ table) {
    int j = blockIdx.x * blockDim.x + threadIdx.x;   // over N*N
    if (j >= NSQ) return;
    int idx = rel[j];
    const float* t = table + idx * HEADS;
#pragma unroll
    for (int h = 0; h < HEADS; h++) {
        g_bias[h * NSQ + j] = t[h];
    }
}

// ---------------- kernel 1: QKV GEMM  (A[16384,256] @ W[256,768]) ----------------
// 64x64 tile, BK=32, 256 threads, 4x4 micro-tile. Scatters into g_q/g_k/g_v
// with head-split layout; q gets 1/sqrt(32) folded in.
__global__ __launch_bounds__(256) void qkv_gemm(const float* __restrict__ A,
                                                const float* __restrict__ W) {
    __shared__ float As[32][68];  // transposed: As[k][m]
    __shared__ float Bs[32][64];  // Bs[k][n]

    const int tid = threadIdx.x;
    const int tx = tid & 15, ty = tid >> 4;
    const int n0 = blockIdx.x * 64;
    const int m0 = blockIdx.y * 64;

    float acc[4][4] = {};

    for (int k0 = 0; k0 < 256; k0 += 32) {
        {
            int col = tid & 31, rb = tid >> 5;
#pragma unroll
            for (int p = 0; p < 8; p++) {
                int row = rb + p * 8;
                As[col][row] = A[(m0 + row) * 256 + k0 + col];
            }
        }
        {
            int nc = tid & 63, kb = tid >> 6;
#pragma unroll
            for (int p = 0; p < 8; p++) {
                int kr = kb + p * 4;
                Bs[kr][nc] = W[(k0 + kr) * 768 + n0 + nc];
            }
        }
        __syncthreads();
#pragma unroll
        for (int k = 0; k < 32; k++) {
            float a[4], b[4];
            *(float4*)a = *(const float4*)&As[k][ty * 4];
            *(float4*)b = *(const float4*)&Bs[k][tx * 4];
#pragma unroll
            for (int ii = 0; ii < 4; ii++)
#pragma unroll
                for (int jj = 0; jj < 4; jj++)
                    acc[ii][jj] += a[ii] * b[jj];
        }
        __syncthreads();
    }

    // epilogue: scatter into q/k/v head layout
    const float scale = 0.17677669529663687f;  // 32^-0.5
    int seg = n0 >> 8;                          // 0=q 1=k 2=v (tile never straddles)
    float* dst = (seg == 0) ? g_q : ((seg == 1) ? g_k : g_v);
    float mul = (seg == 0) ? scale : 1.0f;
    int col = n0 + tx * 4;
    int f = col & 255;
    int h = f >> 5, d = f & 31;
#pragma unroll
    for (int ii = 0; ii < 4; ii++) {
        int m = m0 + ty * 4 + ii;
        int b_ = m >> 10, n_ = m & 1023;
        float4 v4 = make_float4(acc[ii][0] * mul, acc[ii][1] * mul,
                                acc[ii][2] * mul, acc[ii][3] * mul);
        *(float4*)&dst[(((b_ * HEADS + h) * NN + n_) * DMH) + d] = v4;
    }
}

// ---------------- kernel 2: fused flash attention ----------------
// grid: (N/64, B*H). block 256 threads. BM=BN=64, D=32.
__global__ __launch_bounds__(256) void attn_kernel() {
    __shared__ float Qs[32][68];  // Qs[d][row]
    __shared__ float Ks[32][68];  // Ks[d][col]
    __shared__ float Vs[64][32];  // Vs[j][d]
    __shared__ float Ps[64][68];  // Ps[row][j]

    const int bh = blockIdx.y;
    const int h = bh & 7;
    const int q0 = blockIdx.x * 64;
    const float* qptr = g_q + (size_t)bh * NN * DMH;
    const float* kptr = g_k + (size_t)bh * NN * DMH;
    const float* vptr = g_v + (size_t)bh * NN * DMH;
    const float* bptr = g_bias + (size_t)h * NSQ;

    const int tid = threadIdx.x;
    const int tx = tid & 15, ty = tid >> 4;

    // load Q tile transposed
    {
        int col = tid & 31, rb = tid >> 5;
#pragma unroll
        for (int p = 0; p < 8; p++) {
            int row = rb + p * 8;
            Qs[col][row] = qptr[(q0 + row) * DMH + col];
        }
    }

    float m_run[4], l_run[4], o[4][2];
#pragma unroll
    for (int ii = 0; ii < 4; ii++) {
        m_run[ii] = -1e30f;
        l_run[ii] = 0.0f;
        o[ii][0] = 0.0f;
        o[ii][1] = 0.0f;
    }
    __syncthreads();

    for (int kt = 0; kt < 16; kt++) {
        const int k0 = kt * 64;
        {
            int col = tid & 31, rb = tid >> 5;
#pragma unroll
            for (int p = 0; p < 8; p++) {
                int row = rb + p * 8;
                float kv = kptr[(k0 + row) * DMH + col];
                float vv = vptr[(k0 + row) * DMH + col];
                Ks[col][row] = kv;
                Vs[row][col] = vv;
            }
        }
        __syncthreads();

        // S = qk + bias (scale already folded into q)
        float s[4][4];
#pragma unroll
        for (int ii = 0; ii < 4; ii++) {
            int qr = q0 + ty * 4 + ii;
            float4 bv = *(const float4*)&bptr[(size_t)qr * NN + k0 + tx * 4];
            s[ii][0] = bv.x; s[ii][1] = bv.y; s[ii][2] = bv.z; s[ii][3] = bv.w;
        }
#pragma unroll
        for (int k = 0; k < 32; k++) {
            float a[4], b[4];
            *(float4*)a = *(const float4*)&Qs[k][ty * 4];
            *(float4*)b = *(const float4*)&Ks[k][tx * 4];
#pragma unroll
            for (int ii = 0; ii < 4; ii++)
#pragma unroll
                for (int jj = 0; jj < 4; jj++)
                    s[ii][jj] += a[ii] * b[jj];
        }

        // online softmax (row groups live in 16 consecutive lanes, same ty)
#pragma unroll
        for (int ii = 0; ii < 4; ii++) {
            float mx = fmaxf(fmaxf(s[ii][0], s[ii][1]), fmaxf(s[ii][2], s[ii][3]));
#pragma unroll
            for (int off = 1; off < 16; off <<= 1)
                mx = fmaxf(mx, __shfl_xor_sync(0xffffffffu, mx, off));
            float m_new = fmaxf(m_run[ii], mx);
            float corr = __expf(m_run[ii] - m_new);
            float rs = 0.0f;
#pragma unroll
            for (int jj = 0; jj < 4; jj++) {
                s[ii][jj] = __expf(s[ii][jj] - m_new);
                rs += s[ii][jj];
            }
#pragma unroll
            for (int off = 1; off < 16; off <<= 1)
                rs += __shfl_xor_sync(0xffffffffu, rs, off);
            l_run[ii] = l_run[ii] * corr + rs;
            m_run[ii] = m_new;
            o[ii][0] *= corr;
            o[ii][1] *= corr;
            // store P row-major (conflict-free float4 store)
            *(float4*)&Ps[ty * 4 + ii][tx * 4] = *(float4*)s[ii];
        }
        __syncthreads();

        // O += P @ V  (4 rows x 2 d-cols per thread)
#pragma unroll
        for (int j0 = 0; j0 < 64; j0 += 4) {
            float p[4][4];
#pragma unroll
            for (int ii = 0; ii < 4; ii++)
                *(float4*)p[ii] = *(const float4*)&Ps[ty * 4 + ii][j0];
#pragma unroll
            for (int jj = 0; jj < 4; jj++) {
                float2 vv = *(const float2*)&Vs[j0 + jj][tx * 2];
#pragma unroll
                for (int ii = 0; ii < 4; ii++) {
                    o[ii][0] += p[ii][jj] * vv.x;
                    o[ii][1] += p[ii][jj] * vv.y;
                }
            }
        }
        __syncthreads();
    }

    // epilogue: normalize, write to (b, n, h*32+d) layout
    int b_ = bh >> 3;
#pragma unroll
    for (int ii = 0; ii < 4; ii++) {
        int qr = q0 + ty * 4 + ii;
        float inv = 1.0f / l_run[ii];
        float2 r = make_float2(o[ii][0] * inv, o[ii][1] * inv);
        *(float2*)&g_attn[((size_t)(b_ * NN + qr)) * INNER + h * 32 + tx * 2] = r;
    }
}

// ---------------- kernel 3: output projection + bias ----------------
__global__ __launch_bounds__(256) void out_gemm(const float* __restrict__ W,
                                                const float* __restrict__ bias,
                                                float* __restrict__ out) {
    __shared__ float As[32][68];
    __shared__ float Bs[32][64];

    const int tid = threadIdx.x;
    const int tx = tid & 15, ty = tid >> 4;
    const int n0 = blockIdx.x * 64;
    const int m0 = blockIdx.y * 64;

    float acc[4][4] = {};

    for (int k0 = 0; k0 < 256; k0 += 32) {
        {
            int col = tid & 31, rb = tid >> 5;
#pragma unroll
            for (int p = 0; p < 8; p++) {
                int row = rb + p * 8;
                As[col][row] = g_attn[(size_t)(m0 + row) * 256 + k0 + col];
            }
        }
        {
            int nc = tid & 63, kb = tid >> 6;
#pragma unroll
            for (int p = 0; p < 8; p++) {
                int kr = kb + p * 4;
                Bs[kr][nc] = W[(k0 + kr) * 256 + n0 + nc];
            }
        }
        __syncthreads();
#pragma unroll
        for (int k = 0; k < 32; k++) {
            float a[4], b[4];
            *(float4*)a = *(const float4*)&As[k][ty * 4];
            *(float4*)b = *(const float4*)&Bs[k][tx * 4];
#pragma unroll
            for (int ii = 0; ii < 4; ii++)
#pragma unroll
                for (int jj = 0; jj < 4; jj++)
                    acc[ii][jj] += a[ii] * b[jj];
        }
        __syncthreads();
    }

    int col = n0 + tx * 4;
    float4 bv = *(const float4*)&bias[col];
#pragma unroll
    for (int ii = 0; ii < 4; ii++) {
        int m = m0 + ty * 4 + ii;
        float4 v4 = make_float4(acc[ii][0] + bv.x, acc[ii][1] + bv.y,
                                acc[ii][2] + bv.z, acc[ii][3] + bv.w);
        *(float4*)&out[(size_t)m * 256 + col] = v4;
    }
}

// ---------------- launch ----------------
extern "C" void kernel_launch(void* const* d_in, const int* in_sizes, int n_in,
                              void* d_out, int out_size) {
    const float* x      = (const float*)d_in[0];
    const float* w_qkv  = (const float*)d_in[1];
    const float* w_out  = (const float*)d_in[2];
    const float* b_out  = (const float*)d_in[3];
    const float* table  = (const float*)d_in[4];
    const int*   rel    = (const int*)d_in[5];
    float* out = (float*)d_out;

    bias_kernel<<<NSQ / 256, 256>>>(rel, table);
    qkv_gemm<<<dim3(768 / 64, (BB * NN) / 64), 256>>>(x, w_qkv);
    attn_kernel<<<dim3(NN / 64, BB * HEADS), 256>>>();
    out_gemm<<<dim3(256 / 64, (BB * NN) / 64), 256>>>(w_out, b_out, out);
}

// round 2
// speedup vs baseline: 1.5357x; 1.5357x over previous
#include <cuda_runtime.h>
#include <cstdint>

#define BB 16
#define NN 1024
#define INP 256
#define HEADS 8
#define DMH 32
#define INNER 256
#define OUP 256
#define NSQ (NN * NN)

// ---------------- device scratch (allocation-free) ----------------
__device__ float g_q[BB * HEADS * NN * DMH];      // 16 MB, scale pre-applied
__device__ float g_k[BB * HEADS * NN * DMH];      // 16 MB
__device__ float g_v[BB * HEADS * NN * DMH];      // 16 MB
__device__ float g_attn[BB * NN * INNER];         // 16 MB (b, n, h*32+d)
__device__ float g_bias[HEADS * NSQ];             // 32 MB (h, i, j)

// ---------------- helpers ----------------
__device__ __forceinline__ uint32_t f2tf32(float f) {
    uint32_t u;
    asm("cvt.rna.tf32.f32 %0, %1;" : "=r"(u) : "f"(f));
    return u;
}

__device__ __forceinline__ void mma_tf32(float c[4], const uint32_t a[4],
                                         uint32_t b0, uint32_t b1) {
    asm volatile(
        "mma.sync.aligned.m16n8k8.row.col.f32.tf32.tf32.f32 "
        "{%0,%1,%2,%3}, {%4,%5,%6,%7}, {%8,%9}, {%0,%1,%2,%3};"
        : "+f"(c[0]), "+f"(c[1]), "+f"(c[2]), "+f"(c[3])
        : "r"(a[0]), "r"(a[1]), "r"(a[2]), "r"(a[3]), "r"(b0), "r"(b1));
}

// ---------------- kernel 0: bias gather precompute ----------------
__global__ __launch_bounds__(256) void bias_kernel(const int* __restrict__ rel,
                                                   const float* __restrict__ table) {
    int j = blockIdx.x * blockDim.x + threadIdx.x;   // over N*N
    if (j >= NSQ) return;
    int idx = rel[j];
    const float* t = table + idx * HEADS;
#pragma unroll
    for (int h = 0; h < HEADS; h++) {
        g_bias[h * NSQ + j] = t[h];
    }
}

// ---------------- kernel 1: QKV GEMM  (A[16384,256] @ W[256,768]) ----------------
__global__ __launch_bounds__(256) void qkv_gemm(const float* __restrict__ A,
                                                const float* __restrict__ W) {
    __shared__ float As[32][68];  // transposed: As[k][m]
    __shared__ float Bs[32][64];  // Bs[k][n]

    const int tid = threadIdx.x;
    const int tx = tid & 15, ty = tid >> 4;
    const int n0 = blockIdx.x * 64;
    const int m0 = blockIdx.y * 64;

    float acc[4][4] = {};

    for (int k0 = 0; k0 < 256; k0 += 32) {
        {
            int col = tid & 31, rb = tid >> 5;
#pragma unroll
            for (int p = 0; p < 8; p++) {
                int row = rb + p * 8;
                As[col][row] = A[(m0 + row) * 256 + k0 + col];
            }
        }
        {
            int nc = tid & 63, kb = tid >> 6;
#pragma unroll
            for (int p = 0; p < 8; p++) {
                int kr = kb + p * 4;
                Bs[kr][nc] = W[(k0 + kr) * 768 + n0 + nc];
            }
        }
        __syncthreads();
#pragma unroll
        for (int k = 0; k < 32; k++) {
            float a[4], b[4];
            *(float4*)a = *(const float4*)&As[k][ty * 4];
            *(float4*)b = *(const float4*)&Bs[k][tx * 4];
#pragma unroll
            for (int ii = 0; ii < 4; ii++)
#pragma unroll
                for (int jj = 0; jj < 4; jj++)
                    acc[ii][jj] += a[ii] * b[jj];
        }
        __syncthreads();
    }

    const float scale = 0.17677669529663687f;  // 32^-0.5
    int seg = n0 >> 8;                          // 0=q 1=k 2=v
    float* dst = (seg == 0) ? g_q : ((seg == 1) ? g_k : g_v);
    float mul = (seg == 0) ? scale : 1.0f;
    int col = n0 + tx * 4;
    int f = col & 255;
    int h = f >> 5, d = f & 31;
#pragma unroll
    for (int ii = 0; ii < 4; ii++) {
        int m = m0 + ty * 4 + ii;
        int b_ = m >> 10, n_ = m & 1023;
        float4 v4 = make_float4(acc[ii][0] * mul, acc[ii][1] * mul,
                                acc[ii][2] * mul, acc[ii][3] * mul);
        *(float4*)&dst[(((b_ * HEADS + h) * NN + n_) * DMH) + d] = v4;
    }
}

// ---------------- kernel 2: flash attention on tensor cores (tf32 mma.sync) ----
// grid: (N/64, B*H). 128 threads = 4 warps; warp w owns rows [w*16, w*16+16).
__global__ __launch_bounds__(128) void attn_tc() {
    __shared__ float    Qs[64][36];   // raw fp32, padded row (conflict-free frags)
    __shared__ uint32_t Ks[64][36];   // tf32-rounded bits
    __shared__ uint32_t Vs[64][36];   // tf32-rounded bits

    const int tid = threadIdx.x;
    const int lane = tid & 31, wid = tid >> 5;
    const int g = lane >> 2, q = lane & 3;

    const int bh = blockIdx.y;
    const int h = bh & 7, b_ = bh >> 3;
    const int q0 = blockIdx.x * 64;

    const float* qptr = g_q + (size_t)bh * NN * DMH;
    const float* kptr = g_k + (size_t)bh * NN * DMH;
    const float* vptr = g_v + (size_t)bh * NN * DMH;
    const float* bptr = g_bias + (size_t)h * NSQ;

    // ---- load Q tile (64x32), coalesced ----
#pragma unroll
    for (int i = 0; i < 16; i++) {
        int e = tid + i * 128;
        int r = e >> 5, d = e & 31;
        Qs[r][d] = qptr[(q0 + r) * DMH + d];
    }
    __syncthreads();

    // ---- Q A-frags in registers for the whole kernel ----
    const int row0 = wid * 16 + g;
    uint32_t qa[4][4];
#pragma unroll
    for (int ks = 0; ks < 4; ks++) {
        qa[ks][0] = f2tf32(Qs[row0][ks * 8 + q]);
        qa[ks][1] = f2tf32(Qs[row0 + 8][ks * 8 + q]);
        qa[ks][2] = f2tf32(Qs[row0][ks * 8 + q + 4]);
        qa[ks][3] = f2tf32(Qs[row0 + 8][ks * 8 + q + 4]);
    }

    float O[4][4] = {};
    float m0 = -1e30f, m1 = -1e30f, l0 = 0.0f, l1 = 0.0f;

    const float* brow0 = bptr + (size_t)(q0 + row0) * NN;
    const float* brow1 = brow0 + (size_t)8 * NN;
    const int src = (lane & 28) | (q >> 1);

    for (int kt = 0; kt < 16; kt++) {
        const int k0 = kt * 64;
        __syncthreads();  // previous iteration's reads of Ks/Vs done
#pragma unroll
        for (int i = 0; i < 16; i++) {
            int e = tid + i * 128;
            int r = e >> 5, d = e & 31;
            Ks[r][d] = f2tf32(kptr[(k0 + r) * DMH + d]);
            Vs[r][d] = f2tf32(vptr[(k0 + r) * DMH + d]);
        }
        __syncthreads();

        // ---- S = bias; S += Q K^T (scale folded into Q) ----
        float s[8][4];
#pragma unroll
        for (int t = 0; t < 8; t++) {
            float2 b01 = *(const float2*)&brow0[k0 + 8 * t + 2 * q];
            float2 b23 = *(const float2*)&brow1[k0 + 8 * t + 2 * q];
            s[t][0] = b01.x; s[t][1] = b01.y;
            s[t][2] = b23.x; s[t][3] = b23.y;
        }
#pragma unroll
        for (int t = 0; t < 8; t++) {
#pragma unroll
            for (int ks = 0; ks < 4; ks++) {
                uint32_t b0 = Ks[8 * t + g][ks * 8 + q];
                uint32_t b1 = Ks[8 * t + g][ks * 8 + q + 4];
                mma_tf32(s[t], qa[ks], b0, b1);
            }
        }

        // ---- online softmax (rows g and g+8 handled separately) ----
        float rm0 = -1e30f, rm1 = -1e30f;
#pragma unroll
        for (int t = 0; t < 8; t++) {
            rm0 = fmaxf(rm0, fmaxf(s[t][0], s[t][1]));
            rm1 = fmaxf(rm1, fmaxf(s[t][2], s[t][3]));
        }
        rm0 = fmaxf(rm0, __shfl_xor_sync(0xffffffffu, rm0, 1));
        rm0 = fmaxf(rm0, __shfl_xor_sync(0xffffffffu, rm0, 2));
        rm1 = fmaxf(rm1, __shfl_xor_sync(0xffffffffu, rm1, 1));
        rm1 = fmaxf(rm1, __shfl_xor_sync(0xffffffffu, rm1, 2));
        float mn0 = fmaxf(m0, rm0), mn1 = fmaxf(m1, rm1);
        float corr0 = __expf(m0 - mn0), corr1 = __expf(m1 - mn1);
        m0 = mn0; m1 = mn1;

        float rs0 = 0.0f, rs1 = 0.0f;
#pragma unroll
        for (int t = 0; t < 8; t++) {
            s[t][0] = __expf(s[t][0] - mn0);
            s[t][1] = __expf(s[t][1] - mn0);
            s[t][2] = __expf(s[t][2] - mn1);
            s[t][3] = __expf(s[t][3] - mn1);
            rs0 += s[t][0] + s[t][1];
            rs1 += s[t][2] + s[t][3];
        }
        rs0 += __shfl_xor_sync(0xffffffffu, rs0, 1);
        rs0 += __shfl_xor_sync(0xffffffffu, rs0, 2);
        rs1 += __shfl_xor_sync(0xffffffffu, rs1, 1);
        rs1 += __shfl_xor_sync(0xffffffffu, rs1, 2);
        l0 = l0 * corr0 + rs0;
        l1 = l1 * corr1 + rs1;
#pragma unroll
        for (int u = 0; u < 4; u++) {
            O[u][0] *= corr0; O[u][1] *= corr0;
            O[u][2] *= corr1; O[u][3] *= corr1;
        }

        // ---- P (C-frag) -> A-frag via shuffles, then O += P V ----
        const bool odd = (lane & 1) != 0;
#pragma unroll
        for (int t = 0; t < 8; t++) {
            float v00 = __shfl_sync(0xffffffffu, s[t][0], src);
            float v01 = __shfl_sync(0xffffffffu, s[t][1], src);
            float v20 = __shfl_sync(0xffffffffu, s[t][2], src);
            float v21 = __shfl_sync(0xffffffffu, s[t][3], src);
            float w00 = __shfl_sync(0xffffffffu, s[t][0], src + 2);
            float w01 = __shfl_sync(0xffffffffu, s[t][1], src + 2);
            float w20 = __shfl_sync(0xffffffffu, s[t][2], src + 2);
            float w21 = __shfl_sync(0xffffffffu, s[t][3], src + 2);
            uint32_t pa[4];
            pa[0] = f2tf32(odd ? v01 : v00);
            pa[1] = f2tf32(odd ? v21 : v20);
            pa[2] = f2tf32(odd ? w01 : w00);
            pa[3] = f2tf32(odd ? w21 : w20);
#pragma unroll
            for (int u = 0; u < 4; u++) {
                uint32_t b0 = Vs[8 * t + q][8 * u + g];
                uint32_t b1 = Vs[8 * t + q + 4][8 * u + g];
                mma_tf32(O[u], pa, b0, b1);
            }
        }
    }

    // ---- epilogue: normalize, write (b, n, h*32+d) ----
    float inv0 = 1.0f / l0, inv1 = 1.0f / l1;
    int orow = q0 + row0;
#pragma unroll
    for (int u = 0; u < 4; u++) {
        int d = h * 32 + 8 * u + 2 * q;
        *(float2*)&g_attn[((size_t)b_ * NN + orow) * INNER + d] =
            make_float2(O[u][0] * inv0, O[u][1] * inv0);
        *(float2*)&g_attn[((size_t)b_ * NN + orow + 8) * INNER + d] =
            make_float2(O[u][2] * inv1, O[u][3] * inv1);
    }
}

// ---------------- kernel 3: output projection + bias ----------------
__global__ __launch_bounds__(256) void out_gemm(const float* __restrict__ W,
                                                const float* __restrict__ bias,
                                                float* __restrict__ out) {
    __shared__ float As[32][68];
    __shared__ float Bs[32][64];

    const int tid = threadIdx.x;
    const int tx = tid & 15, ty = tid >> 4;
    const int n0 = blockIdx.x * 64;
    const int m0 = blockIdx.y * 64;

    float acc[4][4] = {};

    for (int k0 = 0; k0 < 256; k0 += 32) {
        {
            int col = tid & 31, rb = tid >> 5;
#pragma unroll
            for (int p = 0; p < 8; p++) {
                int row = rb + p * 8;
                As[col][row] = g_attn[(size_t)(m0 + row) * 256 + k0 + col];
            }
        }
        {
            int nc = tid & 63, kb = tid >> 6;
#pragma unroll
            for (int p = 0; p < 8; p++) {
                int kr = kb + p * 4;
                Bs[kr][nc] = W[(k0 + kr) * 256 + n0 + nc];
            }
        }
        __syncthreads();
#pragma unroll
        for (int k = 0; k < 32; k++) {
            float a[4], b[4];
            *(float4*)a = *(const float4*)&As[k][ty * 4];
            *(float4*)b = *(const float4*)&Bs[k][tx * 4];
#pragma unroll
            for (int ii = 0; ii < 4; ii++)
#pragma unroll
                for (int jj = 0; jj < 4; jj++)
                    acc[ii][jj] += a[ii] * b[jj];
        }
        __syncthreads();
    }

    int col = n0 + tx * 4;
    float4 bv = *(const float4*)&bias[col];
#pragma unroll
    for (int ii = 0; ii < 4; ii++) {
        int m = m0 + ty * 4 + ii;
        float4 v4 = make_float4(acc[ii][0] + bv.x, acc[ii][1] + bv.y,
                                acc[ii][2] + bv.z, acc[ii][3] + bv.w);
        *(float4*)&out[(size_t)m * 256 + col] = v4;
    }
}

// ---------------- launch ----------------
extern "C" void kernel_launch(void* const* d_in, const int* in_sizes, int n_in,
                              void* d_out, int out_size) {
    const float* x      = (const float*)d_in[0];
    const float* w_qkv  = (const float*)d_in[1];
    const float* w_out  = (const float*)d_in[2];
    const float* b_out  = (const float*)d_in[3];
    const float* table  = (const float*)d_in[4];
    const int*   rel    = (const int*)d_in[5];
    float* out = (float*)d_out;

    bias_kernel<<<NSQ / 256, 256>>>(rel, table);
    qkv_gemm<<<dim3(768 / 64, (BB * NN) / 64), 256>>>(x, w_qkv);
    attn_tc<<<dim3(NN / 64, BB * HEADS), 128>>>();
    out_gemm<<<dim3(256 / 64, (BB * NN) / 64), 256>>>(w_out, b_out, out);
}

// round 3
// speedup vs baseline: 1.9609x; 1.2768x over previous
#include <cuda_runtime.h>
#include <cstdint>

#define BB 16
#define NN 1024
#define INP 256
#define HEADS 8
#define DMH 32
#define INNER 256
#define OUP 256
#define NTBL 3969   // (2*32-1)^2

// ---------------- device scratch (allocation-free) ----------------
__device__ float g_q[BB * HEADS * NN * DMH];      // 16 MB, scale pre-applied
__device__ float g_k[BB * HEADS * NN * DMH];      // 16 MB
__device__ float g_v[BB * HEADS * NN * DMH];      // 16 MB
__device__ float g_attn[BB * NN * INNER];         // 16 MB (b, n, h*32+d)
__device__ float g_tbl[HEADS * NTBL];             // 127 KB, [h][idx]

// ---------------- helpers ----------------
__device__ __forceinline__ uint32_t f2tf32(float f) {
    uint32_t u;
    asm("cvt.rna.tf32.f32 %0, %1;" : "=r"(u) : "f"(f));
    return u;
}

__device__ __forceinline__ void mma_tf32(float c[4], const uint32_t a[4],
                                         uint32_t b0, uint32_t b1) {
    asm volatile(
        "mma.sync.aligned.m16n8k8.row.col.f32.tf32.tf32.f32 "
        "{%0,%1,%2,%3}, {%4,%5,%6,%7}, {%8,%9}, {%0,%1,%2,%3};"
        : "+f"(c[0]), "+f"(c[1]), "+f"(c[2]), "+f"(c[3])
        : "r"(a[0]), "r"(a[1]), "r"(a[2]), "r"(a[3]), "r"(b0), "r"(b1));
}

// ---------------- kernel 0: transpose bias table to [h][idx] ----------------
__global__ __launch_bounds__(256) void tbl_kernel(const float* __restrict__ table) {
    int t = blockIdx.x * blockDim.x + threadIdx.x;
    if (t >= NTBL * HEADS) return;
    int idx = t >> 3, h = t & 7;
    g_tbl[h * NTBL + idx] = table[t];
}

// ================= high-throughput fp32 SGEMM (128x64 block, 8x4 micro) ======
// A[M,256] row-major, W[256, ldw] row-major. 256 threads.
// ty = tid/16 -> 8 rows, tx = tid%16 -> 4 cols.

// ---------------- kernel 1: QKV GEMM  (A[16384,256] @ W[256,768]) ------------
__global__ __launch_bounds__(256) void qkv_gemm(const float* __restrict__ A,
                                                const float* __restrict__ W) {
    __shared__ float As[32][132];  // As[k][m]
    __shared__ float Bs[32][64];   // Bs[k][n]

    const int tid = threadIdx.x;
    const int tx = tid & 15, ty = tid >> 4;
    const int n0 = blockIdx.x * 64;
    const int m0 = blockIdx.y * 128;

    float acc[8][4] = {};

    for (int k0 = 0; k0 < 256; k0 += 32) {
#pragma unroll
        for (int p = 0; p < 4; p++) {
            int e = tid + p * 256;            // 0..1023 float4s of A tile
            int r = e >> 3, c4 = e & 7;
            float4 v = *(const float4*)&A[(size_t)(m0 + r) * 256 + k0 + c4 * 4];
            As[c4 * 4 + 0][r] = v.x;
            As[c4 * 4 + 1][r] = v.y;
            As[c4 * 4 + 2][r] = v.z;
            As[c4 * 4 + 3][r] = v.w;
        }
#pragma unroll
        for (int p = 0; p < 2; p++) {
            int e = tid + p * 256;            // 0..511 float4s of B tile
            int kr = e >> 4, n4 = e & 15;
            *(float4*)&Bs[kr][n4 * 4] =
                *(const float4*)&W[(size_t)(k0 + kr) * 768 + n0 + n4 * 4];
        }
        __syncthreads();
#pragma unroll
        for (int k = 0; k < 32; k++) {
            float a[8], b[4];
            *(float4*)&a[0] = *(const float4*)&As[k][ty * 8];
            *(float4*)&a[4] = *(const float4*)&As[k][ty * 8 + 4];
            *(float4*)b = *(const float4*)&Bs[k][tx * 4];
#pragma unroll
            for (int ii = 0; ii < 8; ii++)
#pragma unroll
                for (int jj = 0; jj < 4; jj++)
                    acc[ii][jj] += a[ii] * b[jj];
        }
        __syncthreads();
    }

    const float scale = 0.17677669529663687f;  // 32^-0.5
    int seg = n0 >> 8;                          // 0=q 1=k 2=v
    float* dst = (seg == 0) ? g_q : ((seg == 1) ? g_k : g_v);
    float mul = (seg == 0) ? scale : 1.0f;
    int col = n0 + tx * 4;
    int f = col & 255;
    int h = f >> 5, d = f & 31;
#pragma unroll
    for (int ii = 0; ii < 8; ii++) {
        int m = m0 + ty * 8 + ii;
        int b_ = m >> 10, n_ = m & 1023;
        float4 v4 = make_float4(acc[ii][0] * mul, acc[ii][1] * mul,
                                acc[ii][2] * mul, acc[ii][3] * mul);
        *(float4*)&dst[(((b_ * HEADS + h) * NN + n_) * DMH) + d] = v4;
    }
}

// ---------------- kernel 3: output projection + bias -------------------------
__global__ __launch_bounds__(256) void out_gemm(const float* __restrict__ W,
                                                const float* __restrict__ bias,
                                                float* __restrict__ out) {
    __shared__ float As[32][132];
    __shared__ float Bs[32][64];

    const int tid = threadIdx.x;
    const int tx = tid & 15, ty = tid >> 4;
    const int n0 = blockIdx.x * 64;
    const int m0 = blockIdx.y * 128;

    float acc[8][4] = {};

    for (int k0 = 0; k0 < 256; k0 += 32) {
#pragma unroll
        for (int p = 0; p < 4; p++) {
            int e = tid + p * 256;
            int r = e >> 3, c4 = e & 7;
            float4 v = *(const float4*)&g_attn[(size_t)(m0 + r) * 256 + k0 + c4 * 4];
            As[c4 * 4 + 0][r] = v.x;
            As[c4 * 4 + 1][r] = v.y;
            As[c4 * 4 + 2][r] = v.z;
            As[c4 * 4 + 3][r] = v.w;
        }
#pragma unroll
        for (int p = 0; p < 2; p++) {
            int e = tid + p * 256;
            int kr = e >> 4, n4 = e & 15;
            *(float4*)&Bs[kr][n4 * 4] =
                *(const float4*)&W[(size_t)(k0 + kr) * 256 + n0 + n4 * 4];
        }
        __syncthreads();
#pragma unroll
        for (int k = 0; k < 32; k++) {
            float a[8], b[4];
            *(float4*)&a[0] = *(const float4*)&As[k][ty * 8];
            *(float4*)&a[4] = *(const float4*)&As[k][ty * 8 + 4];
            *(float4*)b = *(const float4*)&Bs[k][tx * 4];
#pragma unroll
            for (int ii = 0; ii < 8; ii++)
#pragma unroll
                for (int jj = 0; jj < 4; jj++)
                    acc[ii][jj] += a[ii] * b[jj];
        }
        __syncthreads();
    }

    int col = n0 + tx * 4;
    float4 bv = *(const float4*)&bias[col];
#pragma unroll
    for (int ii = 0; ii < 8; ii++) {
        int m = m0 + ty * 8 + ii;
        float4 v4 = make_float4(acc[ii][0] + bv.x, acc[ii][1] + bv.y,
                                acc[ii][2] + bv.z, acc[ii][3] + bv.w);
        *(float4*)&out[(size_t)m * 256 + col] = v4;
    }
}

// ---------------- kernel 2: flash attention on tensor cores (tf32 mma.sync) ----
// grid: (N/64, B*H). 128 threads = 4 warps; warp w owns rows [w*16, w*16+16).
__global__ __launch_bounds__(128) void attn_tc() {
    __shared__ float    Qs[64][36];   // raw fp32
    __shared__ uint32_t Ks[64][36];   // tf32 bits
    __shared__ uint32_t Vs[64][40];   // tf32 bits (pitch 40: conflict-free PV)

    const int tid = threadIdx.x;
    const int lane = tid & 31, wid = tid >> 5;
    const int g = lane >> 2, q = lane & 3;

    const int bh = blockIdx.y;
    const int h = bh & 7, b_ = bh >> 3;
    const int q0 = blockIdx.x * 64;

    const float* qptr = g_q + (size_t)bh * NN * DMH;
    const float* kptr = g_k + (size_t)bh * NN * DMH;
    const float* vptr = g_v + (size_t)bh * NN * DMH;
    const float* tbh  = g_tbl + h * NTBL;

    // ---- load Q tile (64x32) as float4 ----
    {
        const float4* q4 = (const float4*)(qptr + (size_t)q0 * DMH);
#pragma unroll
        for (int i = 0; i < 4; i++) {
            int e = tid + i * 128;
            int r = e >> 3, c4 = e & 7;
            *(float4*)&Qs[r][c4 * 4] = q4[r * 8 + c4];
        }
    }
    __syncthreads();

    // ---- Q A-frags in registers for the whole kernel ----
    const int row0 = wid * 16 + g;
    uint32_t qa[4][4];
#pragma unroll
    for (int ks = 0; ks < 4; ks++) {
        qa[ks][0] = f2tf32(Qs[row0][ks * 8 + q]);
        qa[ks][1] = f2tf32(Qs[row0 + 8][ks * 8 + q]);
        qa[ks][2] = f2tf32(Qs[row0][ks * 8 + q + 4]);
        qa[ks][3] = f2tf32(Qs[row0 + 8][ks * 8 + q + 4]);
    }

    // bias row constants: idx = C(row) - (63*yj + xj)
    const int i0 = q0 + row0;
    const int i1 = i0 + 8;
    const int C0 = ((i0 >> 5) + 31) * 63 + (i0 & 31) + 31;
    const int C1 = ((i1 >> 5) + 31) * 63 + (i1 & 31) + 31;

    float O[4][4] = {};
    float m0 = -1e30f, m1 = -1e30f, l0 = 0.0f, l1 = 0.0f;
    const int src = (lane & 28) | (q >> 1);

    for (int kt = 0; kt < 16; kt++) {
        const int k0 = kt * 64;
        __syncthreads();  // previous iteration's reads of Ks/Vs done
        {
            const float4* k4 = (const float4*)(kptr + (size_t)k0 * DMH);
            const float4* v4 = (const float4*)(vptr + (size_t)k0 * DMH);
#pragma unroll
            for (int i = 0; i < 4; i++) {
                int e = tid + i * 128;
                int r = e >> 3, c4 = e & 7;
                float4 kv = k4[r * 8 + c4];
                float4 vv = v4[r * 8 + c4];
                uint4 kb = make_uint4(f2tf32(kv.x), f2tf32(kv.y), f2tf32(kv.z), f2tf32(kv.w));
                uint4 vb = make_uint4(f2tf32(vv.x), f2tf32(vv.y), f2tf32(vv.z), f2tf32(vv.w));
                *(uint4*)&Ks[r][c4 * 4] = kb;
                *(uint4*)&Vs[r][c4 * 4] = vb;
            }
        }
        __syncthreads();

        // ---- S = bias (arith rel-index gather, L1-resident table) ----
        float s[8][4];
#pragma unroll
        for (int t = 0; t < 8; t++) {
            int colb = k0 + 8 * t + 2 * q;
            int off = 63 * (colb >> 5) + (colb & 31);
            s[t][0] = tbh[C0 - off];
            s[t][1] = tbh[C0 - off - 1];
            s[t][2] = tbh[C1 - off];
            s[t][3] = tbh[C1 - off - 1];
        }
        // ---- S += Q K^T (scale folded into Q) ----
#pragma unroll
        for (int t = 0; t < 8; t++) {
#pragma unroll
            for (int ks = 0; ks < 4; ks++) {
                uint32_t b0 = Ks[8 * t + g][ks * 8 + q];
                uint32_t b1 = Ks[8 * t + g][ks * 8 + q + 4];
                mma_tf32(s[t], qa[ks], b0, b1);
            }
        }

        // ---- online softmax ----
        float rm0 = -1e30f, rm1 = -1e30f;
#pragma unroll
        for (int t = 0; t < 8; t++) {
            rm0 = fmaxf(rm0, fmaxf(s[t][0], s[t][1]));
            rm1 = fmaxf(rm1, fmaxf(s[t][2], s[t][3]));
        }
        rm0 = fmaxf(rm0, __shfl_xor_sync(0xffffffffu, rm0, 1));
        rm0 = fmaxf(rm0, __shfl_xor_sync(0xffffffffu, rm0, 2));
        rm1 = fmaxf(rm1, __shfl_xor_sync(0xffffffffu, rm1, 1));
        rm1 = fmaxf(rm1, __shfl_xor_sync(0xffffffffu, rm1, 2));
        float mn0 = fmaxf(m0, rm0), mn1 = fmaxf(m1, rm1);
        float corr0 = __expf(m0 - mn0), corr1 = __expf(m1 - mn1);
        m0 = mn0; m1 = mn1;

        float rs0 = 0.0f, rs1 = 0.0f;
#pragma unroll
        for (int t = 0; t < 8; t++) {
            s[t][0] = __expf(s[t][0] - mn0);
            s[t][1] = __expf(s[t][1] - mn0);
            s[t][2] = __expf(s[t][2] - mn1);
            s[t][3] = __expf(s[t][3] - mn1);
            rs0 += s[t][0] + s[t][1];
            rs1 += s[t][2] + s[t][3];
        }
        rs0 += __shfl_xor_sync(0xffffffffu, rs0, 1);
        rs0 += __shfl_xor_sync(0xffffffffu, rs0, 2);
        rs1 += __shfl_xor_sync(0xffffffffu, rs1, 1);
        rs1 += __shfl_xor_sync(0xffffffffu, rs1, 2);
        l0 = l0 * corr0 + rs0;
        l1 = l1 * corr1 + rs1;
#pragma unroll
        for (int u = 0; u < 4; u++) {
            O[u][0] *= corr0; O[u][1] *= corr0;
            O[u][2] *= corr1; O[u][3] *= corr1;
        }

        // ---- P (C-frag) -> A-frag via shuffles, then O += P V ----
        const bool odd = (lane & 1) != 0;
#pragma unroll
        for (int t = 0; t < 8; t++) {
            float v00 = __shfl_sync(0xffffffffu, s[t][0], src);
            float v01 = __shfl_sync(0xffffffffu, s[t][1], src);
            float v20 = __shfl_sync(0xffffffffu, s[t][2], src);
            float v21 = __shfl_sync(0xffffffffu, s[t][3], src);
            float w00 = __shfl_sync(0xffffffffu, s[t][0], src + 2);
            float w01 = __shfl_sync(0xffffffffu, s[t][1], src + 2);
            float w20 = __shfl_sync(0xffffffffu, s[t][2], src + 2);
            float w21 = __shfl_sync(0xffffffffu, s[t][3], src + 2);
            uint32_t pa[4];
            pa[0] = f2tf32(odd ? v01 : v00);
            pa[1] = f2tf32(odd ? v21 : v20);
            pa[2] = f2tf32(odd ? w01 : w00);
            pa[3] = f2tf32(odd ? w21 : w20);
#pragma unroll
            for (int u = 0; u < 4; u++) {
                uint32_t b0 = Vs[8 * t + q][8 * u + g];
                uint32_t b1 = Vs[8 * t + q + 4][8 * u + g];
                mma_tf32(O[u], pa, b0, b1);
            }
        }
    }

    // ---- epilogue: normalize, write (b, n, h*32+d) ----
    float inv0 = 1.0f / l0, inv1 = 1.0f / l1;
    int orow = q0 + row0;
#pragma unroll
    for (int u = 0; u < 4; u++) {
        int d = h * 32 + 8 * u + 2 * q;
        *(float2*)&g_attn[((size_t)b_ * NN + orow) * INNER + d] =
            make_float2(O[u][0] * inv0, O[u][1] * inv0);
        *(float2*)&g_attn[((size_t)b_ * NN + orow + 8) * INNER + d] =
            make_float2(O[u][2] * inv1, O[u][3] * inv1);
    }
}

// ---------------- launch ----------------
extern "C" void kernel_launch(void* const* d_in, const int* in_sizes, int n_in,
                              void* d_out, int out_size) {
    const float* x      = (const float*)d_in[0];
    const float* w_qkv  = (const float*)d_in[1];
    const float* w_out  = (const float*)d_in[2];
    const float* b_out  = (const float*)d_in[3];
    const float* table  = (const float*)d_in[4];
    float* out = (float*)d_out;

    tbl_kernel<<<(NTBL * HEADS + 255) / 256, 256>>>(table);
    qkv_gemm<<<dim3(768 / 64, (BB * NN) / 128), 256>>>(x, w_qkv);
    attn_tc<<<dim3(NN / 64, BB * HEADS), 128>>>();
    out_gemm<<<dim3(256 / 64, (BB * NN) / 128), 256>>>(w_out, b_out, out);
}